// round 1
// baseline (speedup 1.0000x reference)
#include <cuda_runtime.h>
#include <math.h>

#define L 512
#define NCON 20
#define INV_TEMP (1.0f / 0.07f)
#define MAXROWS 32768

// scratch (device globals; no allocation allowed)
__device__ float g_ebar[2][L];       // mean concept embedding per branch
__device__ float g_keep[2][NCON];    // 1.0 except at P_idx entries
__device__ float g_dot0[MAXROWS];    // <row, ebar_sz>
__device__ float g_dot1[MAXROWS];    // <row, ebar_nsz>
__device__ float g_sumsq[MAXROWS];   // ||row||^2
__device__ float g_partial[1024];    // per-block partial sums

// ---------------------------------------------------------------------------
// Kernel 1: build e_bar (mean of selected concept embeddings, duplicates
// counted, matching jnp.mean(all_emb[P_idx])) and keep masks.
// One block, L threads.
// ---------------------------------------------------------------------------
__global__ void prep_kernel(const float* __restrict__ all_emb,
                            const int* __restrict__ Psz, int nPsz,
                            const int* __restrict__ Pnsz, int nPnsz) {
    int t = threadIdx.x;  // 0..L-1
    float s0 = 0.0f, s1 = 0.0f;
    for (int j = 0; j < nPsz; j++)  s0 += all_emb[Psz[j] * L + t];
    for (int j = 0; j < nPnsz; j++) s1 += all_emb[Pnsz[j] * L + t];
    g_ebar[0][t] = s0 / (float)nPsz;
    g_ebar[1][t] = s1 / (float)nPnsz;
    if (t < NCON) { g_keep[0][t] = 1.0f; g_keep[1][t] = 1.0f; }
    __syncthreads();
    if (t == 0) {
        for (int j = 0; j < nPsz; j++)  g_keep[0][Psz[j]]  = 0.0f;
        for (int j = 0; j < nPnsz; j++) g_keep[1][Pnsz[j]] = 0.0f;
    }
}

// ---------------------------------------------------------------------------
// Kernel 2: streaming pass over hg. One warp per row (512 floats = 4 float4
// per lane). Computes sumsq, dot with ebar_sz, dot with ebar_nsz.
// This is the HBM-bound kernel: reads 64 MB, writes 384 KB.
// ---------------------------------------------------------------------------
__global__ void rowpass_kernel(const float* __restrict__ hg, int nrows) {
    int warp = (blockIdx.x * blockDim.x + threadIdx.x) >> 5;
    int lane = threadIdx.x & 31;
    if (warp >= nrows) return;

    const float4* row = reinterpret_cast<const float4*>(hg + (size_t)warp * L);
    const float4* e0p = reinterpret_cast<const float4*>(g_ebar[0]);
    const float4* e1p = reinterpret_cast<const float4*>(g_ebar[1]);

    float ss = 0.0f, d0 = 0.0f, d1 = 0.0f;
#pragma unroll
    for (int it = 0; it < 4; it++) {
        int idx = it * 32 + lane;
        float4 v  = row[idx];
        float4 e0 = e0p[idx];
        float4 e1 = e1p[idx];
        ss = fmaf(v.x, v.x, fmaf(v.y, v.y, fmaf(v.z, v.z, fmaf(v.w, v.w, ss))));
        d0 = fmaf(v.x, e0.x, fmaf(v.y, e0.y, fmaf(v.z, e0.z, fmaf(v.w, e0.w, d0))));
        d1 = fmaf(v.x, e1.x, fmaf(v.y, e1.y, fmaf(v.z, e1.z, fmaf(v.w, e1.w, d1))));
    }
#pragma unroll
    for (int o = 16; o > 0; o >>= 1) {
        ss += __shfl_xor_sync(0xffffffffu, ss, o);
        d0 += __shfl_xor_sync(0xffffffffu, d0, o);
        d1 += __shfl_xor_sync(0xffffffffu, d1, o);
    }
    if (lane == 0) {
        g_sumsq[warp] = ss;
        g_dot0[warp]  = d0;
        g_dot1[warp]  = d1;
    }
}

// ---------------------------------------------------------------------------
// Kernel 3: gathered per-index terms + deterministic per-block partial sums.
// Blocks [0, Bsz) handle sz branch, [Bsz, Bsz+Bn) handle nsz branch.
// term_i = log(den_i) - dot_i / (||row|| tau)
// ---------------------------------------------------------------------------
__global__ void gather_kernel(const int* __restrict__ sz_idx, int Ns,
                              const int* __restrict__ nsz_idx, int Nn,
                              const float* __restrict__ corr, int Bsz) {
    int b = blockIdx.x;
    int branch = (b < Bsz) ? 0 : 1;
    int base = (branch ? (b - Bsz) : b) * (int)blockDim.x;
    int i = base + threadIdx.x;
    const int* idxp = branch ? nsz_idx : sz_idx;
    int count = branch ? Nn : Ns;

    float val = 0.0f;
    if (i < count) {
        int r = idxp[i];
        float invn = 1.0f / fmaxf(sqrtf(g_sumsq[r]), 1e-12f);
        float dot  = (branch ? g_dot1[r] : g_dot0[r]) * invn;
        const float* cr = corr + (size_t)r * NCON;
        const float* keep = g_keep[branch];
        float den = 0.0f;
#pragma unroll
        for (int c = 0; c < NCON; c++)
            den += expf(cr[c] * INV_TEMP) * keep[c];
        val = logf(den) - dot * INV_TEMP;
    }

    // fixed-tree block reduction (deterministic)
    __shared__ float sh[256];
    sh[threadIdx.x] = val;
    __syncthreads();
    for (int s = 128; s > 0; s >>= 1) {
        if (threadIdx.x < s) sh[threadIdx.x] += sh[threadIdx.x + s];
        __syncthreads();
    }
    if (threadIdx.x == 0) g_partial[b] = sh[0];
}

// ---------------------------------------------------------------------------
// Kernel 4: finalize. Fixed-tree reduce of partials, scale by 1/Ns and 1/Nn.
// ---------------------------------------------------------------------------
__global__ void finalize_kernel(float* __restrict__ out, int Bsz, int Btot,
                                float invNs, float invNn) {
    __shared__ float sh[1024];
    int t = threadIdx.x;  // 1024 threads
    float v = 0.0f;
    if (t < Btot) v = g_partial[t] * ((t < Bsz) ? invNs : invNn);
    sh[t] = v;
    __syncthreads();
    for (int s = 512; s > 0; s >>= 1) {
        if (t < s) sh[t] += sh[t + s];
        __syncthreads();
    }
    if (t == 0) out[0] = sh[0];
}

extern "C" void kernel_launch(void* const* d_in, const int* in_sizes, int n_in,
                              void* d_out, int out_size) {
    const float* hg       = (const float*)d_in[0];
    const float* corr     = (const float*)d_in[1];
    const float* all_emb  = (const float*)d_in[2];
    const int*   sz_idx   = (const int*)d_in[3];
    const int*   nsz_idx  = (const int*)d_in[4];
    const int*   Psz_idx  = (const int*)d_in[5];
    const int*   Pnsz_idx = (const int*)d_in[6];
    float* out = (float*)d_out;

    int nrows = in_sizes[0] / L;          // 32768
    int Ns    = in_sizes[3];
    int Nn    = in_sizes[4];
    int nPsz  = in_sizes[5];
    int nPnsz = in_sizes[6];

    prep_kernel<<<1, L>>>(all_emb, Psz_idx, nPsz, Pnsz_idx, nPnsz);

    int threads = 256;                    // 8 warps -> 8 rows per block
    int blocks = (nrows + 7) / 8;
    rowpass_kernel<<<blocks, threads>>>(hg, nrows);

    int Bsz = (Ns + 255) / 256;
    int Bn  = (Nn + 255) / 256;
    gather_kernel<<<Bsz + Bn, 256>>>(sz_idx, Ns, nsz_idx, Nn, corr, Bsz);

    finalize_kernel<<<1, 1024>>>(out, Bsz, Bsz + Bn,
                                 1.0f / (float)Ns, 1.0f / (float)Nn);
}